// round 15
// baseline (speedup 1.0000x reference)
#include <cuda_runtime.h>
#include <math.h>

#define Bsz  16
#define Tlen 1024
#define Hdim 512
#define NA   64
#define NC   64
#define NBLK (NA + NC)

__device__ float g_out0[(size_t)Bsz * Tlen * Hdim];
__device__ float g_h0buf[2][Bsz * Hdim];
__device__ float g_h1buf[2][Bsz * Hdim];
__device__ unsigned int g_leafA[8 * 64], g_leafC[8 * 64];
__device__ unsigned int g_topA, g_topC;

union F4U2 { float4 f; ulonglong2 u; };

__device__ __forceinline__ unsigned long long ffma2(unsigned long long a,
                                                    unsigned long long b,
                                                    unsigned long long c) {
    unsigned long long d;
    asm("fma.rn.f32x2 %0, %1, %2, %3;" : "=l"(d) : "l"(a), "l"(b), "l"(c));
    return d;
}
__device__ __forceinline__ void unpk2(unsigned long long v, float& lo, float& hi) {
    asm("mov.b64 {%0, %1}, %2;" : "=f"(lo), "=f"(hi) : "l"(v));
}
__device__ __forceinline__ unsigned int ld_acq(const unsigned int* p) {
    unsigned int v;
    asm volatile("ld.acquire.gpu.global.u32 %0, [%1];" : "=r"(v) : "l"(p) : "memory");
    return v;
}
__device__ __forceinline__ void arrive_tree(unsigned int* leaf, unsigned int* top,
                                            unsigned int target8) {
    unsigned int old;
    asm volatile("atom.acq_rel.gpu.global.add.u32 %0, [%1], 1;"
                 : "=r"(old) : "l"(leaf) : "memory");
    if (old == target8 - 1u)
        asm volatile("red.release.gpu.global.add.u32 [%0], 1;" :: "l"(top) : "memory");
}
__device__ __forceinline__ void cp16(unsigned int smem_dst, const void* gsrc) {
    asm volatile("cp.async.cg.shared.global [%0], [%1], 16;"
                 :: "r"(smem_dst), "l"(gsrc) : "memory");
}
#define CP_COMMIT() asm volatile("cp.async.commit_group;" ::: "memory")
#define CP_WAIT0()  asm volatile("cp.async.wait_group 0;" ::: "memory")

__device__ __forceinline__ float sigm_(float x) {
    return __fdividef(1.0f, 1.0f + __expf(-x));
}
__device__ __forceinline__ float tanh_(float x) {
    float e = __expf(2.0f * fminf(fmaxf(x, -9.0f), 9.0f));
    return __fdividef(e - 1.0f, e + 1.0f);
}

__global__ void reset_sync() {
    if (threadIdx.x < 8) { g_leafA[threadIdx.x * 64] = 0u; g_leafC[threadIdx.x * 64] = 0u; }
    if (threadIdx.x == 0) { g_topA = 0u; g_topC = 0u; }
}

// smem floats: wih 16384 | h 8704 | iw 2*8704 | part 10368 | c 128 | bias 32 = 53024
#define SCAN_SMEM (53024 * 4)

__global__ __launch_bounds__(256, 1) void lstm_fused(
    const float* __restrict__ x,
    const float* __restrict__ w_ih0, const float* __restrict__ w_hh0,
    const float* __restrict__ b_ih0, const float* __restrict__ b_hh0,
    const float* __restrict__ w_ih1, const float* __restrict__ w_hh1,
    const float* __restrict__ b_ih1, const float* __restrict__ b_hh1,
    const float* __restrict__ h0, const float* __restrict__ c0,
    float* __restrict__ out)
{
    extern __shared__ float smem[];
    const int tid = threadIdx.x, lane = tid & 31;
    const int kwid = tid >> 5, ksl = lane >> 4, rslot = lane & 15;
    const bool isA = (blockIdx.x < NA);
    const int gbid = isA ? blockIdx.x : blockIdx.x - NA;
    const int jb = gbid * 8;
    unsigned int* myLeaf = (isA ? g_leafA : g_leafC) + (gbid & 7) * 64;
    unsigned int* myTop  = isA ? &g_topA : &g_topC;

    float* wih_s  = smem;                   // 16384
    float* h_all  = wih_s + 16384;          // 8704
    float* iw_all = h_all + 8704;           // 2*8704 (A double-buffers; C uses buf0)
    float* part   = iw_all + 17408;         // 10368
    float* c_s    = part + 10368;           // 128
    float* bias_s = c_s + 128;              // 32
    float* hw = h_all + kwid * 1088;        // [16 b][64 k] pitch 68
    const unsigned int hw_sm = (unsigned int)__cvta_generic_to_shared(hw);
    const unsigned int iw_sm = (unsigned int)__cvta_generic_to_shared(iw_all);

    const float* whh  = isA ? w_hh0 : w_hh1;
    const float* wih  = isA ? w_ih0 : w_ih1;
    const float* bih  = isA ? b_ih0 : b_ih1;
    const float* bhh  = isA ? b_hh0 : b_hh1;
    const float* isrc = isA ? x : (const float*)g_out0;
    float (*hbuf)[Bsz * Hdim] = isA ? g_h0buf : g_h1buf;
    const int lo = isA ? 0 : Bsz * Hdim;

    // W_hh slice into registers (rows rslot, rslot+16)
    unsigned long long w0[16], w1[16];
    {
        const int g0 = (rslot >> 3) * Hdim + jb + (rslot & 7);
        const int g1 = ((rslot + 16) >> 3) * Hdim + jb + ((rslot + 16) & 7);
        const float* p0 = &whh[(size_t)g0 * Hdim + kwid * 64 + ksl * 32];
        const float* p1 = &whh[(size_t)g1 * Hdim + kwid * 64 + ksl * 32];
#pragma unroll
        for (int kp = 0; kp < 8; kp++) {
            F4U2 a; a.f = *(const float4*)&p0[kp * 4];
            w0[2 * kp] = a.u.x; w0[2 * kp + 1] = a.u.y;
            F4U2 b; b.f = *(const float4*)&p1[kp * 4];
            w1[2 * kp] = b.u.x; w1[2 * kp + 1] = b.u.y;
        }
    }
    // W_ih slice into smem
#pragma unroll
    for (int i = 0; i < 16; i++) {
        int idx = tid + 256 * i, kq = idx >> 5, row = idx & 31;
        int grow = (row >> 3) * Hdim + jb + (row & 7);
        *(float4*)&wih_s[(size_t)(kq * 32 + row) * 4] =
            *(const float4*)&wih[(size_t)grow * Hdim + kq * 4];
    }
    if (tid < 32) {
        int grow = (tid >> 3) * Hdim + jb + (tid & 7);
        bias_s[tid] = bih[grow] + bhh[grow];
    }
    if (tid < 128) {
        int jj = tid >> 4, b = tid & 15;
        c_s[tid] = c0[lo + b * Hdim + jb + jj];
    }
    __syncthreads();

    // prologue: stage iw(0) into buf0
    if (!isA) {
        if (lane == 0) while (ld_acq(&g_topA) < 8u) { }
        __syncwarp();
    }
#pragma unroll
    for (int i = 0; i < 8; i++) {
        int idx = lane + 32 * i, b = idx >> 4, q = idx & 15;
        cp16(iw_sm + (kwid * 1088 + b * 68 + q * 4) * 4,
             &isrc[(size_t)(b * Tlen) * Hdim + kwid * 64 + q * 4]);
    }
    CP_COMMIT(); CP_WAIT0();
    __syncwarp();

    for (int t = 0; t < Tlen; t++) {
        // A: issue iw(t+1) cp.async at step start (no dependency, no wait here)
        if (isA && t + 1 < Tlen) {
            const unsigned int dst = iw_sm + (((t + 1) & 1) * 8704 + kwid * 1088) * 4;
#pragma unroll
            for (int i = 0; i < 8; i++) {
                int idx = lane + 32 * i, b = idx >> 4, q = idx & 15;
                cp16(dst + (b * 68 + q * 4) * 4,
                     &isrc[(size_t)(b * Tlen + t + 1) * Hdim + kwid * 64 + q * 4]);
            }
            CP_COMMIT();
        }
        const float* iwr = iw_all + (isA ? (t & 1) * 8704 : 0) + kwid * 1088;

        unsigned long long acc0[16], acc1[16];
#pragma unroll
        for (int b = 0; b < 16; b++) { acc0[b] = 0ull; acc1[b] = 0ull; }

        // ih dot, first half (kp 0-3) — hides own-group barrier skew
#pragma unroll
        for (int kp = 0; kp < 4; kp++) {
            const int kq = kwid * 16 + ksl * 8 + kp;
            F4U2 wa; wa.f = *(const float4*)&wih_s[(size_t)(kq * 32 + rslot) * 4];
            F4U2 wb; wb.f = *(const float4*)&wih_s[(size_t)(kq * 32 + rslot + 16) * 4];
#pragma unroll
            for (int b = 0; b < 16; b++) {
                F4U2 o4; o4.f = *(const float4*)&iwr[b * 68 + ksl * 32 + kp * 4];
                acc0[b] = ffma2(wa.u.x, o4.u.x, acc0[b]);
                acc0[b] = ffma2(wa.u.y, o4.u.y, acc0[b]);
                acc1[b] = ffma2(wb.u.x, o4.u.x, acc1[b]);
                acc1[b] = ffma2(wb.u.y, o4.u.y, acc1[b]);
            }
        }

        // poll + launch h copy (latency hidden under second ih half)
        if (lane == 0 && t > 0) while (ld_acq(myTop) < 8u * (unsigned)t) { }
        __syncwarp();
        {
            const float* hsrc = (t == 0) ? (h0 + lo) : hbuf[t & 1];
#pragma unroll
            for (int i = 0; i < 8; i++) {
                int idx = lane + 32 * i, b = idx >> 4, q = idx & 15;
                cp16(hw_sm + (b * 68 + q * 4) * 4,
                     &hsrc[b * Hdim + kwid * 64 + q * 4]);
            }
            CP_COMMIT();
        }

        // ih dot, second half (kp 4-7)
#pragma unroll
        for (int kp = 4; kp < 8; kp++) {
            const int kq = kwid * 16 + ksl * 8 + kp;
            F4U2 wa; wa.f = *(const float4*)&wih_s[(size_t)(kq * 32 + rslot) * 4];
            F4U2 wb; wb.f = *(const float4*)&wih_s[(size_t)(kq * 32 + rslot + 16) * 4];
#pragma unroll
            for (int b = 0; b < 16; b++) {
                F4U2 o4; o4.f = *(const float4*)&iwr[b * 68 + ksl * 32 + kp * 4];
                acc0[b] = ffma2(wa.u.x, o4.u.x, acc0[b]);
                acc0[b] = ffma2(wa.u.y, o4.u.y, acc0[b]);
                acc1[b] = ffma2(wb.u.x, o4.u.x, acc1[b]);
                acc1[b] = ffma2(wb.u.y, o4.u.y, acc1[b]);
            }
        }
        CP_WAIT0();
        __syncwarp();

        // hh dot (unchanged)
#pragma unroll
        for (int kp = 0; kp < 8; kp++) {
#pragma unroll
            for (int b = 0; b < 16; b++) {
                F4U2 h4; h4.f = *(const float4*)&hw[b * 68 + ksl * 32 + kp * 4];
                acc0[b] = ffma2(w0[2 * kp],     h4.u.x, acc0[b]);
                acc0[b] = ffma2(w0[2 * kp + 1], h4.u.y, acc0[b]);
                acc1[b] = ffma2(w1[2 * kp],     h4.u.x, acc1[b]);
                acc1[b] = ffma2(w1[2 * kp + 1], h4.u.y, acc1[b]);
            }
        }
        // partials
        {
            const int ks = kwid * 2 + ksl;
            float v0[16], v1[16];
#pragma unroll
            for (int b = 0; b < 16; b++) {
                float plo, phi;
                unpk2(acc0[b], plo, phi); v0[b] = plo + phi;
                unpk2(acc1[b], plo, phi); v1[b] = plo + phi;
            }
            float4* p0 = (float4*)&part[ks * 648 + rslot * 20];
            float4* p1 = (float4*)&part[ks * 648 + (rslot + 16) * 20];
#pragma unroll
            for (int j = 0; j < 4; j++) {
                p0[j] = make_float4(v0[4*j], v0[4*j+1], v0[4*j+2], v0[4*j+3]);
                p1[j] = make_float4(v1[4*j], v1[4*j+1], v1[4*j+2], v1[4*j+3]);
            }
        }
        __syncthreads();

        // cell (warps 0-3) || C: warps 4-7 stage iw(t+1)
        if (tid < 128) {
            int jj = tid >> 4, b = tid & 15;
            float vi = 0.f, vf = 0.f, vg = 0.f, vo = 0.f;
#pragma unroll
            for (int k2 = 0; k2 < 16; k2++) {
                const float* pk = &part[k2 * 648 + b];
                vi += pk[(0  + jj) * 20];
                vf += pk[(8  + jj) * 20];
                vg += pk[(16 + jj) * 20];
                vo += pk[(24 + jj) * 20];
            }
            vi += bias_s[jj];      vf += bias_s[8 + jj];
            vg += bias_s[16 + jj]; vo += bias_s[24 + jj];
            float ig = sigm_(vi), fg = sigm_(vf);
            float gg = tanh_(vg), og = sigm_(vo);
            float c = fg * c_s[tid] + ig * gg;
            c_s[tid] = c;
            float h = og * tanh_(c);
            int col = jb + jj;
            __stcg(&hbuf[(t + 1) & 1][b * Hdim + col], h);
            if (isA) __stcg(&g_out0[(size_t)(b * Tlen + t) * Hdim + col], h);
            if (t == Tlen - 1) out[lo + b * Hdim + col] = h;
            // early arrival: h published; don't wait for staging warps
            asm volatile("bar.sync 1, 128;" ::: "memory");
            if (tid == 0 && (isA || t < Tlen - 1))
                arrive_tree(myLeaf, myTop, 8u * (unsigned)(t + 1));
        } else if (!isA && t + 1 < Tlen) {
            // C: stage out0(t+1) into iw buf0 (all 8 regions) during the cell
            if (lane == 0) while (ld_acq(&g_topA) < 8u * (unsigned)(t + 2)) { }
            __syncwarp();
            int idx = tid - 128;  // 0..127
#pragma unroll
            for (int i = 0; i < 16; i++) {
                int j = i * 128 + idx;
                int w = j >> 8, b = (j >> 4) & 15, q = j & 15;
                cp16(iw_sm + (w * 1088 + b * 68 + q * 4) * 4,
                     &g_out0[(size_t)(b * Tlen + t + 1) * Hdim + w * 64 + q * 4]);
            }
            CP_COMMIT(); CP_WAIT0();
        }
        __syncthreads();
    }
}

// ---------------------------------------------------------------------------
extern "C" void kernel_launch(void* const* d_in, const int* in_sizes, int n_in,
                              void* d_out, int out_size)
{
    const float* x     = (const float*)d_in[0];
    const float* h0    = (const float*)d_in[1];
    const float* c0    = (const float*)d_in[2];
    const float* w_ih0 = (const float*)d_in[3];
    const float* w_hh0 = (const float*)d_in[4];
    const float* b_ih0 = (const float*)d_in[5];
    const float* b_hh0 = (const float*)d_in[6];
    const float* w_ih1 = (const float*)d_in[7];
    const float* w_hh1 = (const float*)d_in[8];
    const float* b_ih1 = (const float*)d_in[9];
    const float* b_hh1 = (const float*)d_in[10];
    float* out = (float*)d_out;

    cudaFuncSetAttribute(lstm_fused, cudaFuncAttributeMaxDynamicSharedMemorySize,
                         SCAN_SMEM);

    reset_sync<<<1, 32>>>();
    lstm_fused<<<NBLK, 256, SCAN_SMEM>>>(x,
                                         w_ih0, w_hh0, b_ih0, b_hh0,
                                         w_ih1, w_hh1, b_ih1, b_hh1,
                                         h0, c0, out);
}

// round 16
// speedup vs baseline: 1.0886x; 1.0886x over previous
#include <cuda_runtime.h>
#include <math.h>

#define Bsz  16
#define Tlen 1024
#define Hdim 512
#define NA   64
#define NC   64
#define NBLK (NA + NC)

__device__ float g_out0[(size_t)Bsz * Tlen * Hdim];
__device__ float g_h0buf[2][Bsz * Hdim];
__device__ float g_h1buf[2][Bsz * Hdim];
__device__ unsigned int g_leafA[8 * 64], g_leafC[8 * 64];
__device__ unsigned int g_topA, g_topC;

union F4U2 { float4 f; ulonglong2 u; };

__device__ __forceinline__ unsigned long long ffma2(unsigned long long a,
                                                    unsigned long long b,
                                                    unsigned long long c) {
    unsigned long long d;
    asm("fma.rn.f32x2 %0, %1, %2, %3;" : "=l"(d) : "l"(a), "l"(b), "l"(c));
    return d;
}
__device__ __forceinline__ void unpk2(unsigned long long v, float& lo, float& hi) {
    asm("mov.b64 {%0, %1}, %2;" : "=f"(lo), "=f"(hi) : "l"(v));
}
__device__ __forceinline__ unsigned int ld_acq(const unsigned int* p) {
    unsigned int v;
    asm volatile("ld.acquire.gpu.global.u32 %0, [%1];" : "=r"(v) : "l"(p) : "memory");
    return v;
}
__device__ __forceinline__ void arrive_tree(unsigned int* leaf, unsigned int* top,
                                            unsigned int target8) {
    unsigned int old;
    asm volatile("atom.acq_rel.gpu.global.add.u32 %0, [%1], 1;"
                 : "=r"(old) : "l"(leaf) : "memory");
    if (old == target8 - 1u)
        asm volatile("red.release.gpu.global.add.u32 [%0], 1;" :: "l"(top) : "memory");
}
__device__ __forceinline__ float sigm_(float x) {
    return __fdividef(1.0f, 1.0f + __expf(-x));
}
__device__ __forceinline__ float tanh_(float x) {
    float e = __expf(2.0f * fminf(fmaxf(x, -9.0f), 9.0f));
    return __fdividef(e - 1.0f, e + 1.0f);
}

__global__ void reset_sync() {
    if (threadIdx.x < 8) { g_leafA[threadIdx.x * 64] = 0u; g_leafC[threadIdx.x * 64] = 0u; }
    if (threadIdx.x == 0) { g_topA = 0u; g_topC = 0u; }
}

// smem floats: wih 16384 | h 8704 | iw 8704 | part 10368 | c 128 | bias 32 = 44320
#define SCAN_SMEM (44320 * 4)

__global__ __launch_bounds__(256, 1) void lstm_fused(
    const float* __restrict__ x,       // (B, T, 512)
    const float* __restrict__ w_ih0, const float* __restrict__ w_hh0,
    const float* __restrict__ b_ih0, const float* __restrict__ b_hh0,
    const float* __restrict__ w_ih1, const float* __restrict__ w_hh1,
    const float* __restrict__ b_ih1, const float* __restrict__ b_hh1,
    const float* __restrict__ h0, const float* __restrict__ c0,
    float* __restrict__ out)
{
    extern __shared__ float smem[];
    const int tid = threadIdx.x, lane = tid & 31;
    const int kwid = tid >> 5, ksl = lane >> 4, rslot = lane & 15;
    const bool isA = (blockIdx.x < NA);
    const int gbid = isA ? blockIdx.x : blockIdx.x - NA;
    const int jb = gbid * 8;
    unsigned int* myLeaf = (isA ? g_leafA : g_leafC) + (gbid & 7) * 64;
    unsigned int* myTop  = isA ? &g_topA : &g_topC;

    float* wih_s  = smem;                   // 16384
    float* h_all  = wih_s + 16384;          // 8704
    float* iw_all = h_all + 8704;           // 8704 (x for A, out0 for C)
    float* part   = iw_all + 8704;          // 10368
    float* c_s    = part + 10368;           // 128
    float* bias_s = c_s + 128;              // 32
    float* hw = h_all + kwid * 1088;        // [16 b][64 k] pitch 68
    float* iw = iw_all + kwid * 1088;

    const float* whh  = isA ? w_hh0 : w_hh1;
    const float* wih  = isA ? w_ih0 : w_ih1;
    const float* bih  = isA ? b_ih0 : b_ih1;
    const float* bhh  = isA ? b_hh0 : b_hh1;
    const float* isrc = isA ? x : (const float*)g_out0;   // [b*Tlen+t][512]
    float (*hbuf)[Bsz * Hdim] = isA ? g_h0buf : g_h1buf;
    const int lo = isA ? 0 : Bsz * Hdim;

    // W_hh slice into registers (rows rslot, rslot+16)
    unsigned long long w0[16], w1[16];
    {
        const int g0 = (rslot >> 3) * Hdim + jb + (rslot & 7);
        const int g1 = ((rslot + 16) >> 3) * Hdim + jb + ((rslot + 16) & 7);
        const float* p0 = &whh[(size_t)g0 * Hdim + kwid * 64 + ksl * 32];
        const float* p1 = &whh[(size_t)g1 * Hdim + kwid * 64 + ksl * 32];
#pragma unroll
        for (int kp = 0; kp < 8; kp++) {
            F4U2 a; a.f = *(const float4*)&p0[kp * 4];
            w0[2 * kp] = a.u.x; w0[2 * kp + 1] = a.u.y;
            F4U2 b; b.f = *(const float4*)&p1[kp * 4];
            w1[2 * kp] = b.u.x; w1[2 * kp + 1] = b.u.y;
        }
    }
    // W_ih slice into smem: [(kq*32+row)*4], kq 0..127
#pragma unroll
    for (int i = 0; i < 16; i++) {
        int idx = tid + 256 * i, kq = idx >> 5, row = idx & 31;
        int grow = (row >> 3) * Hdim + jb + (row & 7);
        *(float4*)&wih_s[(size_t)(kq * 32 + row) * 4] =
            *(const float4*)&wih[(size_t)grow * Hdim + kq * 4];
    }
    if (tid < 32) {
        int grow = (tid >> 3) * Hdim + jb + (tid & 7);
        bias_s[tid] = bih[grow] + bhh[grow];
    }
    if (tid < 128) {
        int jj = tid >> 4, b = tid & 15;
        c_s[tid] = c0[lo + b * Hdim + jb + jj];
    }
    __syncthreads();

    // prologue: stage iw(0) (A: x[0], no wait; C: out0[0] after A step 0)
    if (!isA) {
        if (lane == 0) while (ld_acq(&g_topA) < 8u) { }
        __syncwarp();
    }
#pragma unroll
    for (int i = 0; i < 8; i++) {
        int idx = lane + 32 * i, b = idx >> 4, q = idx & 15;
        float4 v = __ldcg((const float4*)&isrc[(size_t)(b * Tlen) * Hdim + kwid * 64 + q * 4]);
        *(float4*)&iw[b * 68 + q * 4] = v;
    }
    __syncwarp();

    for (int t = 0; t < Tlen; t++) {
        unsigned long long acc0[16], acc1[16];
#pragma unroll
        for (int b = 0; b < 16; b++) { acc0[b] = 0ull; acc1[b] = 0ull; }

        // ih dot on staged iw (hides own-group barrier settle)
#pragma unroll
        for (int kp = 0; kp < 8; kp++) {
            const int kq = kwid * 16 + ksl * 8 + kp;
            F4U2 wa; wa.f = *(const float4*)&wih_s[(size_t)(kq * 32 + rslot) * 4];
            F4U2 wb; wb.f = *(const float4*)&wih_s[(size_t)(kq * 32 + rslot + 16) * 4];
#pragma unroll
            for (int b = 0; b < 16; b++) {
                F4U2 o4; o4.f = *(const float4*)&iw[b * 68 + ksl * 32 + kp * 4];
                acc0[b] = ffma2(wa.u.x, o4.u.x, acc0[b]);
                acc0[b] = ffma2(wa.u.y, o4.u.y, acc0[b]);
                acc1[b] = ffma2(wb.u.x, o4.u.x, acc1[b]);
                acc1[b] = ffma2(wb.u.y, o4.u.y, acc1[b]);
            }
        }

        // own-group gate + stage h (per warp)
        if (lane == 0 && t > 0) while (ld_acq(myTop) < 8u * (unsigned)t) { }
        __syncwarp();
        const float* hsrc = (t == 0) ? (h0 + lo) : hbuf[t & 1];
#pragma unroll
        for (int i = 0; i < 8; i++) {
            int idx = lane + 32 * i, b = idx >> 4, q = idx & 15;
            float4 v = __ldcg((const float4*)&hsrc[b * Hdim + kwid * 64 + q * 4]);
            *(float4*)&hw[b * 68 + q * 4] = v;
        }
        __syncwarp();

        // hh dot
#pragma unroll
        for (int kp = 0; kp < 8; kp++) {
#pragma unroll
            for (int b = 0; b < 16; b++) {
                F4U2 h4; h4.f = *(const float4*)&hw[b * 68 + ksl * 32 + kp * 4];
                acc0[b] = ffma2(w0[2 * kp],     h4.u.x, acc0[b]);
                acc0[b] = ffma2(w0[2 * kp + 1], h4.u.y, acc0[b]);
                acc1[b] = ffma2(w1[2 * kp],     h4.u.x, acc1[b]);
                acc1[b] = ffma2(w1[2 * kp + 1], h4.u.y, acc1[b]);
            }
        }
        // partials
        {
            const int ks = kwid * 2 + ksl;
            float v0[16], v1[16];
#pragma unroll
            for (int b = 0; b < 16; b++) {
                float plo, phi;
                unpk2(acc0[b], plo, phi); v0[b] = plo + phi;
                unpk2(acc1[b], plo, phi); v1[b] = plo + phi;
            }
            float4* p0 = (float4*)&part[ks * 648 + rslot * 20];
            float4* p1 = (float4*)&part[ks * 648 + (rslot + 16) * 20];
#pragma unroll
            for (int j = 0; j < 4; j++) {
                p0[j] = make_float4(v0[4*j], v0[4*j+1], v0[4*j+2], v0[4*j+3]);
                p1[j] = make_float4(v1[4*j], v1[4*j+1], v1[4*j+2], v1[4*j+3]);
            }
        }
        __syncthreads();

        // cell (warps 0-3): reduce folded in; EARLY arrival right after h publish
        if (tid < 128) {
            int jj = tid >> 4, b = tid & 15;
            float vi = 0.f, vf = 0.f, vg = 0.f, vo = 0.f;
#pragma unroll
            for (int k2 = 0; k2 < 16; k2++) {
                const float* pk = &part[k2 * 648 + b];
                vi += pk[(0  + jj) * 20];
                vf += pk[(8  + jj) * 20];
                vg += pk[(16 + jj) * 20];
                vo += pk[(24 + jj) * 20];
            }
            vi += bias_s[jj];      vf += bias_s[8 + jj];
            vg += bias_s[16 + jj]; vo += bias_s[24 + jj];
            float ig = sigm_(vi), fg = sigm_(vf);
            float gg = tanh_(vg), og = sigm_(vo);
            float c = fg * c_s[tid] + ig * gg;
            c_s[tid] = c;
            float h = og * tanh_(c);
            int col = jb + jj;
            __stcg(&hbuf[(t + 1) & 1][b * Hdim + col], h);
            if (isA) __stcg(&g_out0[(size_t)(b * Tlen + t) * Hdim + col], h);
            if (t == Tlen - 1) out[lo + b * Hdim + col] = h;
            // sync cell warps only, then publish — staging no longer gates arrival
            asm volatile("bar.sync 1, 128;" ::: "memory");
            if (tid == 0 && (isA || t < Tlen - 1))
                arrive_tree(myLeaf, myTop, 8u * (unsigned)(t + 1));
        }

        // stage iw(t+1): A needs nothing; C waits for A step t+1
        if (t + 1 < Tlen) {
            if (!isA) {
                if (lane == 0) while (ld_acq(&g_topA) < 8u * (unsigned)(t + 2)) { }
                __syncwarp();
            }
#pragma unroll
            for (int i = 0; i < 8; i++) {
                int idx = lane + 32 * i, b = idx >> 4, q = idx & 15;
                float4 v = __ldcg((const float4*)&isrc[(size_t)(b * Tlen + t + 1) * Hdim + kwid * 64 + q * 4]);
                *(float4*)&iw[b * 68 + q * 4] = v;
            }
        }
        __syncthreads();
    }
}

// ---------------------------------------------------------------------------
extern "C" void kernel_launch(void* const* d_in, const int* in_sizes, int n_in,
                              void* d_out, int out_size)
{
    const float* x     = (const float*)d_in[0];
    const float* h0    = (const float*)d_in[1];
    const float* c0    = (const float*)d_in[2];
    const float* w_ih0 = (const float*)d_in[3];
    const float* w_hh0 = (const float*)d_in[4];
    const float* b_ih0 = (const float*)d_in[5];
    const float* b_hh0 = (const float*)d_in[6];
    const float* w_ih1 = (const float*)d_in[7];
    const float* w_hh1 = (const float*)d_in[8];
    const float* b_ih1 = (const float*)d_in[9];
    const float* b_hh1 = (const float*)d_in[10];
    float* out = (float*)d_out;

    cudaFuncSetAttribute(lstm_fused, cudaFuncAttributeMaxDynamicSharedMemorySize,
                         SCAN_SMEM);

    reset_sync<<<1, 32>>>();
    lstm_fused<<<NBLK, 256, SCAN_SMEM>>>(x,
                                         w_ih0, w_hh0, b_ih0, b_hh0,
                                         w_ih1, w_hh1, b_ih1, b_hh1,
                                         h0, c0, out);
}

// round 17
// speedup vs baseline: 1.2903x; 1.1852x over previous
#include <cuda_runtime.h>
#include <math.h>

#define Bsz  16
#define Tlen 1024
#define Hdim 512
#define NA   64
#define NC   64
#define NBLK (NA + NC)

__device__ float g_out0[(size_t)Bsz * Tlen * Hdim];
__device__ float g_h0buf[2][Bsz * Hdim];
__device__ float g_h1buf[2][Bsz * Hdim];
__device__ unsigned int g_leafA[8 * 64], g_leafC[8 * 64];   // leaf L = producers of col block L

union F4U2 { float4 f; ulonglong2 u; };

__device__ __forceinline__ unsigned long long ffma2(unsigned long long a,
                                                    unsigned long long b,
                                                    unsigned long long c) {
    unsigned long long d;
    asm("fma.rn.f32x2 %0, %1, %2, %3;" : "=l"(d) : "l"(a), "l"(b), "l"(c));
    return d;
}
__device__ __forceinline__ void unpk2(unsigned long long v, float& lo, float& hi) {
    asm("mov.b64 {%0, %1}, %2;" : "=f"(lo), "=f"(hi) : "l"(v));
}
__device__ __forceinline__ unsigned int ld_acq(const unsigned int* p) {
    unsigned int v;
    asm volatile("ld.acquire.gpu.global.u32 %0, [%1];" : "=r"(v) : "l"(p) : "memory");
    return v;
}
__device__ __forceinline__ void red_rel(unsigned int* p) {
    asm volatile("red.release.gpu.global.add.u32 [%0], 1;" :: "l"(p) : "memory");
}
__device__ __forceinline__ float sigm_(float x) {
    return __fdividef(1.0f, 1.0f + __expf(-x));
}
__device__ __forceinline__ float tanh_(float x) {
    float e = __expf(2.0f * fminf(fmaxf(x, -9.0f), 9.0f));
    return __fdividef(e - 1.0f, e + 1.0f);
}

__global__ void reset_sync() {
    if (threadIdx.x < 8) { g_leafA[threadIdx.x * 64] = 0u; g_leafC[threadIdx.x * 64] = 0u; }
}

// smem floats: wih 16384 | h 8704 | iw 8704 | part 10368 | c 128 | bias 32 = 44320
#define SCAN_SMEM (44320 * 4)

__global__ __launch_bounds__(256, 1) void lstm_fused(
    const float* __restrict__ x,       // (B, T, 512)
    const float* __restrict__ w_ih0, const float* __restrict__ w_hh0,
    const float* __restrict__ b_ih0, const float* __restrict__ b_hh0,
    const float* __restrict__ w_ih1, const float* __restrict__ w_hh1,
    const float* __restrict__ b_ih1, const float* __restrict__ b_hh1,
    const float* __restrict__ h0, const float* __restrict__ c0,
    float* __restrict__ out)
{
    extern __shared__ float smem[];
    const int tid = threadIdx.x, lane = tid & 31;
    const int kwid = tid >> 5, ksl = lane >> 4, rslot = lane & 15;
    const bool isA = (blockIdx.x < NA);
    const int gbid = isA ? blockIdx.x : blockIdx.x - NA;
    const int jb = gbid * 8;
    unsigned int* myLeaves = isA ? g_leafA : g_leafC;
    unsigned int* arrLeaf  = myLeaves + (gbid >> 3) * 64;   // this CTA's producer leaf
    unsigned int* pollLeaf = myLeaves + kwid * 64;          // producers of my k-columns

    float* wih_s  = smem;                   // 16384
    float* h_all  = wih_s + 16384;          // 8704
    float* iw_all = h_all + 8704;           // 8704 (x for A, out0 for C)
    float* part   = iw_all + 8704;          // 10368
    float* c_s    = part + 10368;           // 128
    float* bias_s = c_s + 128;              // 32
    float* hw = h_all + kwid * 1088;        // [16 b][64 k] pitch 68
    float* iw = iw_all + kwid * 1088;

    const float* whh  = isA ? w_hh0 : w_hh1;
    const float* wih  = isA ? w_ih0 : w_ih1;
    const float* bih  = isA ? b_ih0 : b_ih1;
    const float* bhh  = isA ? b_hh0 : b_hh1;
    const float* isrc = isA ? x : (const float*)g_out0;   // [b*Tlen+t][512]
    float (*hbuf)[Bsz * Hdim] = isA ? g_h0buf : g_h1buf;
    const int lo = isA ? 0 : Bsz * Hdim;

    // W_hh slice into registers (rows rslot, rslot+16)
    unsigned long long w0[16], w1[16];
    {
        const int g0 = (rslot >> 3) * Hdim + jb + (rslot & 7);
        const int g1 = ((rslot + 16) >> 3) * Hdim + jb + ((rslot + 16) & 7);
        const float* p0 = &whh[(size_t)g0 * Hdim + kwid * 64 + ksl * 32];
        const float* p1 = &whh[(size_t)g1 * Hdim + kwid * 64 + ksl * 32];
#pragma unroll
        for (int kp = 0; kp < 8; kp++) {
            F4U2 a; a.f = *(const float4*)&p0[kp * 4];
            w0[2 * kp] = a.u.x; w0[2 * kp + 1] = a.u.y;
            F4U2 b; b.f = *(const float4*)&p1[kp * 4];
            w1[2 * kp] = b.u.x; w1[2 * kp + 1] = b.u.y;
        }
    }
    // W_ih slice into smem: [(kq*32+row)*4], kq 0..127
#pragma unroll
    for (int i = 0; i < 16; i++) {
        int idx = tid + 256 * i, kq = idx >> 5, row = idx & 31;
        int grow = (row >> 3) * Hdim + jb + (row & 7);
        *(float4*)&wih_s[(size_t)(kq * 32 + row) * 4] =
            *(const float4*)&wih[(size_t)grow * Hdim + kq * 4];
    }
    if (tid < 32) {
        int grow = (tid >> 3) * Hdim + jb + (tid & 7);
        bias_s[tid] = bih[grow] + bhh[grow];
    }
    if (tid < 128) {
        int jj = tid >> 4, b = tid & 15;
        c_s[tid] = c0[lo + b * Hdim + jb + jj];
    }
    __syncthreads();

    // prologue: stage iw(0) (A: x[0], no wait; C: out0[0] after A step 0 cols)
    if (!isA) {
        if (lane == 0) while (ld_acq(&g_leafA[kwid * 64]) < 8u) { }
        __syncwarp();
    }
#pragma unroll
    for (int i = 0; i < 8; i++) {
        int idx = lane + 32 * i, b = idx >> 4, q = idx & 15;
        float4 v = __ldcg((const float4*)&isrc[(size_t)(b * Tlen) * Hdim + kwid * 64 + q * 4]);
        *(float4*)&iw[b * 68 + q * 4] = v;
    }
    __syncwarp();

    for (int t = 0; t < Tlen; t++) {
        unsigned long long acc0[16], acc1[16];
#pragma unroll
        for (int b = 0; b < 16; b++) { acc0[b] = 0ull; acc1[b] = 0ull; }

        // ih dot on staged iw (hides own-group arrival settle)
#pragma unroll
        for (int kp = 0; kp < 8; kp++) {
            const int kq = kwid * 16 + ksl * 8 + kp;
            F4U2 wa; wa.f = *(const float4*)&wih_s[(size_t)(kq * 32 + rslot) * 4];
            F4U2 wb; wb.f = *(const float4*)&wih_s[(size_t)(kq * 32 + rslot + 16) * 4];
#pragma unroll
            for (int b = 0; b < 16; b++) {
                F4U2 o4; o4.f = *(const float4*)&iw[b * 68 + ksl * 32 + kp * 4];
                acc0[b] = ffma2(wa.u.x, o4.u.x, acc0[b]);
                acc0[b] = ffma2(wa.u.y, o4.u.y, acc0[b]);
                acc1[b] = ffma2(wb.u.x, o4.u.x, acc1[b]);
                acc1[b] = ffma2(wb.u.y, o4.u.y, acc1[b]);
            }
        }

        // gate on MY producers only, then stage h (per warp)
        if (lane == 0 && t > 0) while (ld_acq(pollLeaf) < 8u * (unsigned)t) { }
        __syncwarp();
        const float* hsrc = (t == 0) ? (h0 + lo) : hbuf[t & 1];
#pragma unroll
        for (int i = 0; i < 8; i++) {
            int idx = lane + 32 * i, b = idx >> 4, q = idx & 15;
            float4 v = __ldcg((const float4*)&hsrc[b * Hdim + kwid * 64 + q * 4]);
            *(float4*)&hw[b * 68 + q * 4] = v;
        }
        __syncwarp();

        // hh dot
#pragma unroll
        for (int kp = 0; kp < 8; kp++) {
#pragma unroll
            for (int b = 0; b < 16; b++) {
                F4U2 h4; h4.f = *(const float4*)&hw[b * 68 + ksl * 32 + kp * 4];
                acc0[b] = ffma2(w0[2 * kp],     h4.u.x, acc0[b]);
                acc0[b] = ffma2(w0[2 * kp + 1], h4.u.y, acc0[b]);
                acc1[b] = ffma2(w1[2 * kp],     h4.u.x, acc1[b]);
                acc1[b] = ffma2(w1[2 * kp + 1], h4.u.y, acc1[b]);
            }
        }
        // partials
        {
            const int ks = kwid * 2 + ksl;
            float v0[16], v1[16];
#pragma unroll
            for (int b = 0; b < 16; b++) {
                float plo, phi;
                unpk2(acc0[b], plo, phi); v0[b] = plo + phi;
                unpk2(acc1[b], plo, phi); v1[b] = plo + phi;
            }
            float4* p0 = (float4*)&part[ks * 648 + rslot * 20];
            float4* p1 = (float4*)&part[ks * 648 + (rslot + 16) * 20];
#pragma unroll
            for (int j = 0; j < 4; j++) {
                p0[j] = make_float4(v0[4*j], v0[4*j+1], v0[4*j+2], v0[4*j+3]);
                p1[j] = make_float4(v1[4*j], v1[4*j+1], v1[4*j+2], v1[4*j+3]);
            }
        }
        __syncthreads();

        // cell (warps 0-3): reduce folded in
        if (tid < 128) {
            int jj = tid >> 4, b = tid & 15;
            float vi = 0.f, vf = 0.f, vg = 0.f, vo = 0.f;
#pragma unroll
            for (int k2 = 0; k2 < 16; k2++) {
                const float* pk = &part[k2 * 648 + b];
                vi += pk[(0  + jj) * 20];
                vf += pk[(8  + jj) * 20];
                vg += pk[(16 + jj) * 20];
                vo += pk[(24 + jj) * 20];
            }
            vi += bias_s[jj];      vf += bias_s[8 + jj];
            vg += bias_s[16 + jj]; vo += bias_s[24 + jj];
            float ig = sigm_(vi), fg = sigm_(vf);
            float gg = tanh_(vg), og = sigm_(vo);
            float c = fg * c_s[tid] + ig * gg;
            c_s[tid] = c;
            float h = og * tanh_(c);
            int col = jb + jj;
            __stcg(&hbuf[(t + 1) & 1][b * Hdim + col], h);
            if (isA) __stcg(&g_out0[(size_t)(b * Tlen + t) * Hdim + col], h);
            if (t == Tlen - 1) out[lo + b * Hdim + col] = h;
        }

        // stage iw(t+1): A needs nothing; C waits for its A producers' step t+1
        if (t + 1 < Tlen) {
            if (!isA) {
                if (lane == 0) while (ld_acq(&g_leafA[kwid * 64]) < 8u * (unsigned)(t + 2)) { }
                __syncwarp();
            }
#pragma unroll
            for (int i = 0; i < 8; i++) {
                int idx = lane + 32 * i, b = idx >> 4, q = idx & 15;
                float4 v = __ldcg((const float4*)&isrc[(size_t)(b * Tlen + t + 1) * Hdim + kwid * 64 + q * 4]);
                *(float4*)&iw[b * 68 + q * 4] = v;
            }
        }
        __syncthreads();

        // arrival: single release-red on this CTA's producer leaf
        if (tid == 0 && (isA || t < Tlen - 1))
            red_rel(arrLeaf);
    }
}

// ---------------------------------------------------------------------------
extern "C" void kernel_launch(void* const* d_in, const int* in_sizes, int n_in,
                              void* d_out, int out_size)
{
    const float* x     = (const float*)d_in[0];
    const float* h0    = (const float*)d_in[1];
    const float* c0    = (const float*)d_in[2];
    const float* w_ih0 = (const float*)d_in[3];
    const float* w_hh0 = (const float*)d_in[4];
    const float* b_ih0 = (const float*)d_in[5];
    const float* b_hh0 = (const float*)d_in[6];
    const float* w_ih1 = (const float*)d_in[7];
    const float* w_hh1 = (const float*)d_in[8];
    const float* b_ih1 = (const float*)d_in[9];
    const float* b_hh1 = (const float*)d_in[10];
    float* out = (float*)d_out;

    cudaFuncSetAttribute(lstm_fused, cudaFuncAttributeMaxDynamicSharedMemorySize,
                         SCAN_SMEM);

    reset_sync<<<1, 32>>>();
    lstm_fused<<<NBLK, 256, SCAN_SMEM>>>(x,
                                         w_ih0, w_hh0, b_ih0, b_hh0,
                                         w_ih1, w_hh1, b_ih1, b_hh1,
                                         h0, c0, out);
}